// round 7
// baseline (speedup 1.0000x reference)
#include <cuda_runtime.h>

#define N_G 256
#define D 1024
#define D4 (D / 4)
#define KSPLIT 16
#define KSLICE (D / KSPLIT)   // 64

#define BM 64
#define BN 64
#define BK 16

#define ROWS_A 4088
#define ROWS_B 4091
#define CHUNK 8
#define NCH_A ((ROWS_A + CHUNK - 1) / CHUNK)   // 511
#define NCH_B ((ROWS_B + CHUNK - 1) / CHUNK)   // 512

// Static device scratch (zero-initialized at load; re-zeroed by the pipeline
// itself so every kernel_launch call starts from the same state).
__device__ float g_Asum[N_G * D];              // UNSCALED group sums of im
__device__ float g_Bsum[N_G * D];              // UNSCALED group sums of s
__device__ float g_invA[N_G], g_invB[N_G];     // 1/num_clips, 1/num_caps
__device__ float g_diag[N_G];                  // unscaled diagonal of S
__device__ float g_Sp[KSPLIT][N_G * N_G];      // split-K partial S (plain STG, no zero needed)

// ---- packed fp32x2 helpers (sm_100+; ptxas never auto-fuses these) --------
__device__ __forceinline__ unsigned long long pack2(float lo, float hi) {
    unsigned long long r;
    asm("mov.b64 %0, {%1, %2};" : "=l"(r) : "f"(lo), "f"(hi));
    return r;
}
__device__ __forceinline__ unsigned long long ffma2(unsigned long long a,
                                                    unsigned long long b,
                                                    unsigned long long c) {
    unsigned long long d;
    asm("fma.rn.f32x2 %0, %1, %2, %3;" : "=l"(d) : "l"(a), "l"(b), "l"(c));
    return d;
}
__device__ __forceinline__ void unpack2(float& lo, float& hi, unsigned long long v) {
    asm("mov.b64 {%0, %1}, %2;" : "=f"(lo), "=f"(hi) : "l"(v));
}

// ---------------------------------------------------------------------------
// K1: balanced segmented sums, self-contained (no prep kernel).
//     Each CTA owns CHUNK=8 consecutive rows (blocks [0,511) -> im,
//     [511,1023) -> s). 256 threads = one float4 column each.
//     Row loads are front-batched BEFORE the offset scan so the scan hides
//     under DRAM latency. Block 0 also zeroes g_diag/out and writes g_inv*.
// ---------------------------------------------------------------------------
__global__ __launch_bounds__(256)
void k_seg(const float* __restrict__ im, const float* __restrict__ s,
           const int* __restrict__ ncl, const int* __restrict__ nca,
           float* __restrict__ out) {
    int b = blockIdx.x;
    bool isB = (b >= NCH_A);
    int cb = isB ? b - NCH_A : b;
    int Rtot = isB ? ROWS_B : ROWS_A;
    int r0 = cb * CHUNK;
    int t = threadIdx.x;

    int nrows = Rtot - r0; if (nrows > CHUNK) nrows = CHUNK;

    // ---- front-batched loads (addresses independent of the scan) ----
    const float4* src = (const float4*)(isB ? s : im) + (size_t)r0 * D4 + t;
    float4 v[CHUNK];
#pragma unroll
    for (int u = 0; u < CHUNK; u++)
        v[u] = (u < nrows) ? src[(size_t)u * D4] : make_float4(0.f, 0.f, 0.f, 0.f);

    // ---- per-CTA redundant prefix scan of this side's counts ----
    __shared__ int sa[N_G];
    __shared__ int soff[N_G + 1];
    const int* cnts = isB ? nca : ncl;
    int c = cnts[t];
    sa[t] = c;
    if (b == 0) {
        g_diag[t] = 0.f;
        g_invA[t] = 1.f / (float)ncl[t];
        g_invB[t] = 1.f / (float)nca[t];
        if (t == 0) out[0] = 0.f;
    }
    __syncthreads();
    for (int d = 1; d < N_G; d <<= 1) {
        int va = (t >= d) ? sa[t - d] : 0;
        __syncthreads();
        sa[t] += va;
        __syncthreads();
    }
    soff[t + 1] = sa[t];
    if (t == 0) soff[0] = 0;
    __syncthreads();

    // ---- find group of r0, then segment-walk the 8 rows ----
    int lo = 0, hi = N_G - 1;
    while (lo < hi) {
        int mid = (lo + hi + 1) >> 1;
        if (soff[mid] <= r0) lo = mid; else hi = mid - 1;
    }
    int gidx = lo;
    int gend = soff[gidx + 1];
    float* gs = isB ? g_Bsum : g_Asum;

    float4 acc = make_float4(0.f, 0.f, 0.f, 0.f);
#pragma unroll
    for (int u = 0; u < CHUNK; u++) {
        if (u < nrows && r0 + u == gend) {
            float* p = gs + (size_t)gidx * D + t * 4;
            atomicAdd(p + 0, acc.x); atomicAdd(p + 1, acc.y);
            atomicAdd(p + 2, acc.z); atomicAdd(p + 3, acc.w);
            acc = make_float4(0.f, 0.f, 0.f, 0.f);
            gidx++; gend = soff[gidx + 1];
        }
        acc.x += v[u].x; acc.y += v[u].y; acc.z += v[u].z; acc.w += v[u].w;
    }
    float* p = gs + (size_t)gidx * D + t * 4;
    atomicAdd(p + 0, acc.x); atomicAdd(p + 1, acc.y);
    atomicAdd(p + 2, acc.z); atomicAdd(p + 3, acc.w);
}

// ---------------------------------------------------------------------------
// K2: split-K GEMM with packed fp32x2 FFMA.
//     grid (4,4,16), 256 threads, 64x64 tile, 4x4 micro per thread held as
//     2 row-pairs x 4 cols of f32x2 accumulators.
// ---------------------------------------------------------------------------
__global__ __launch_bounds__(256)
void k_gemm() {
    __shared__ float As[BK][BM];
    __shared__ float Bs[BK][BN];

    int ib = blockIdx.x, jb = blockIdx.y, kz = blockIdx.z;
    int tid = threadIdx.x;
    int tx = tid & 15;
    int ty = tid >> 4;
    int lm = tid & 63;
    int lk = (tid >> 6) << 2;

    const float4* Ag = (const float4*)g_Asum;
    const float4* Bg = (const float4*)g_Bsum;

    unsigned long long accp[2][4];
#pragma unroll
    for (int rp = 0; rp < 2; rp++)
#pragma unroll
        for (int cc = 0; cc < 4; cc++) accp[rp][cc] = pack2(0.f, 0.f);

    int k0base = kz * KSLICE;
    for (int kc = 0; kc < KSLICE; kc += BK) {
        int kq = (k0base + kc + lk) >> 2;
        float4 av = Ag[(ib * BM + lm) * D4 + kq];
        float4 bv = Bg[(jb * BN + lm) * D4 + kq];
        __syncthreads();
        As[lk + 0][lm] = av.x; As[lk + 1][lm] = av.y;
        As[lk + 2][lm] = av.z; As[lk + 3][lm] = av.w;
        Bs[lk + 0][lm] = bv.x; Bs[lk + 1][lm] = bv.y;
        Bs[lk + 2][lm] = bv.z; Bs[lk + 3][lm] = bv.w;
        __syncthreads();

#pragma unroll
        for (int kk = 0; kk < BK; kk++) {
            float4 a4 = *(const float4*)&As[kk][ty << 2];
            float4 b4 = *(const float4*)&Bs[kk][tx << 2];
            unsigned long long a01 = pack2(a4.x, a4.y);
            unsigned long long a23 = pack2(a4.z, a4.w);
            unsigned long long bb0 = pack2(b4.x, b4.x);
            unsigned long long bb1 = pack2(b4.y, b4.y);
            unsigned long long bb2 = pack2(b4.z, b4.z);
            unsigned long long bb3 = pack2(b4.w, b4.w);
            accp[0][0] = ffma2(a01, bb0, accp[0][0]);
            accp[0][1] = ffma2(a01, bb1, accp[0][1]);
            accp[0][2] = ffma2(a01, bb2, accp[0][2]);
            accp[0][3] = ffma2(a01, bb3, accp[0][3]);
            accp[1][0] = ffma2(a23, bb0, accp[1][0]);
            accp[1][1] = ffma2(a23, bb1, accp[1][1]);
            accp[1][2] = ffma2(a23, bb2, accp[1][2]);
            accp[1][3] = ffma2(a23, bb3, accp[1][3]);
        }
    }

    // unpack: accp[rp][c] = (out[2rp][c], out[2rp+1][c])
    float o[4][4];
#pragma unroll
    for (int rp = 0; rp < 2; rp++)
#pragma unroll
        for (int cc = 0; cc < 4; cc++)
            unpack2(o[2 * rp][cc], o[2 * rp + 1][cc], accp[rp][cc]);

    float* Sp = g_Sp[kz];
#pragma unroll
    for (int r = 0; r < 4; r++) {
        int i = ib * BM + (ty << 2) + r;
        float4 vv = make_float4(o[r][0], o[r][1], o[r][2], o[r][3]);
        *(float4*)&Sp[i * N_G + jb * BN + (tx << 2)] = vv;
    }

    if (ib == jb && tx == ty) {
#pragma unroll
        for (int r = 0; r < 4; r++)
            atomicAdd(&g_diag[ib * BM + (ty << 2) + r], o[r][r]);
    }
}

// ---------------------------------------------------------------------------
// K3: loss (count-scaling folded in) + FULL re-zero of g_Asum/g_Bsum.
//     grid 64 x 256; each thread = one (i, j-quad), 16 independent LDG.128.
//     Each thread zeroes 4 float4s per buffer (16384 thr x 4 = 65536 quads
//     = N_G*D floats -> complete coverage; this was the R5 replay bug).
// ---------------------------------------------------------------------------
__global__ __launch_bounds__(256)
void k_loss(float* __restrict__ out) {
    int qid = blockIdx.x * 256 + threadIdx.x;   // [0, 16384)
    int i  = qid >> 6;                          // row
    int j0 = (qid & 63) << 2;                   // first col of the quad

    float4 sv = make_float4(0.f, 0.f, 0.f, 0.f);
#pragma unroll
    for (int z = 0; z < KSPLIT; z++) {
        float4 pv = *(const float4*)&g_Sp[z][i * N_G + j0];
        sv.x += pv.x; sv.y += pv.y; sv.z += pv.z; sv.w += pv.w;
    }

    float ai = g_invA[i];
    float bi = g_invB[i];
    float di = g_diag[i] * ai * bi;

    float4 dj4 = *(const float4*)&g_diag[j0];
    float4 aj4 = *(const float4*)&g_invA[j0];
    float4 bj4 = *(const float4*)&g_invB[j0];

    float sum = 0.f;
    {
        float S, dj;
        S = sv.x * ai * bj4.x; dj = dj4.x * aj4.x * bj4.x;
        if (i != j0 + 0) sum += fmaxf(S - di, 0.f) + fmaxf(S - dj, 0.f);
        S = sv.y * ai * bj4.y; dj = dj4.y * aj4.y * bj4.y;
        if (i != j0 + 1) sum += fmaxf(S - di, 0.f) + fmaxf(S - dj, 0.f);
        S = sv.z * ai * bj4.z; dj = dj4.z * aj4.z * bj4.z;
        if (i != j0 + 2) sum += fmaxf(S - di, 0.f) + fmaxf(S - dj, 0.f);
        S = sv.w * ai * bj4.w; dj = dj4.w * aj4.w * bj4.w;
        if (i != j0 + 3) sum += fmaxf(S - di, 0.f) + fmaxf(S - dj, 0.f);
    }

    // FULL re-zero of accumulators for the next graph replay.
    // N_G*D floats = 65536 float4s; 16384 threads x 4 strided quads each.
    float4 z4 = make_float4(0.f, 0.f, 0.f, 0.f);
#pragma unroll
    for (int u = 0; u < 4; u++) {
        ((float4*)g_Asum)[qid + u * 16384] = z4;
        ((float4*)g_Bsum)[qid + u * 16384] = z4;
    }

#pragma unroll
    for (int st = 16; st > 0; st >>= 1)
        sum += __shfl_xor_sync(0xFFFFFFFF, sum, st);

    __shared__ float red[8];
    int t = threadIdx.x;
    if ((t & 31) == 0) red[t >> 5] = sum;
    __syncthreads();
    if (t < 8) {
        float v = red[t];
#pragma unroll
        for (int st = 4; st > 0; st >>= 1)
            v += __shfl_xor_sync(0xFF, v, st);
        if (t == 0) atomicAdd(out, v);
    }
}

// ---------------------------------------------------------------------------
extern "C" void kernel_launch(void* const* d_in, const int* in_sizes, int n_in,
                              void* d_out, int out_size) {
    const float* im  = (const float*)d_in[0];
    const float* s   = (const float*)d_in[1];
    const int*   ncl = (const int*)d_in[2];
    const int*   nca = (const int*)d_in[3];
    float* out = (float*)d_out;

    k_seg<<<NCH_A + NCH_B, 256>>>(im, s, ncl, nca, out);
    dim3 g2(N_G / BM, N_G / BN, KSPLIT);
    k_gemm<<<g2, 256>>>();
    k_loss<<<64, 256>>>(out);
}

// round 9
// speedup vs baseline: 1.0977x; 1.0977x over previous
#include <cuda_runtime.h>

#define N_G 256
#define D 1024
#define D4 (D / 4)
#define KSPLIT 16
#define KSLICE (D / KSPLIT)   // 64

#define BM 64
#define BN 64
#define BK 16

#define ROWS_A 4088
#define ROWS_B 4091
#define CHUNK 16
#define NCH_A ((ROWS_A + CHUNK - 1) / CHUNK)   // 256
#define NCH_B ((ROWS_B + CHUNK - 1) / CHUNK)   // 256

// Static device scratch (zero-initialized at load; re-zeroed by the pipeline
// itself so every kernel_launch call starts from the same state).
__device__ float g_Asum[N_G * D];              // UNSCALED group sums of im
__device__ float g_Bsum[N_G * D];              // UNSCALED group sums of s
__device__ float g_invA[N_G], g_invB[N_G];     // 1/num_clips, 1/num_caps
__device__ float g_diag[N_G];                  // unscaled diagonal of S
__device__ float g_Sp[KSPLIT][N_G * N_G];      // split-K partial S (plain STG)

// ---- packed fp32x2 helpers (sm_100+; ptxas never auto-fuses these) --------
__device__ __forceinline__ unsigned long long pack2(float lo, float hi) {
    unsigned long long r;
    asm("mov.b64 %0, {%1, %2};" : "=l"(r) : "f"(lo), "f"(hi));
    return r;
}
__device__ __forceinline__ unsigned long long ffma2(unsigned long long a,
                                                    unsigned long long b,
                                                    unsigned long long c) {
    unsigned long long d;
    asm("fma.rn.f32x2 %0, %1, %2, %3;" : "=l"(d) : "l"(a), "l"(b), "l"(c));
    return d;
}
__device__ __forceinline__ void unpack2(float& lo, float& hi, unsigned long long v) {
    asm("mov.b64 {%0, %1}, %2;" : "=f"(lo), "=f"(hi) : "l"(v));
}

// ---------------------------------------------------------------------------
// K1: balanced segmented sums. Each CTA owns CHUNK=16 consecutive rows
//     (blocks [0,256) -> im, [256,512) -> s); 512 CTAs fit in ONE wave at
//     5 CTAs/SM. 256 threads = one float4 column each. Rows loaded in two
//     front-batched batches of 8. Count prefix-scan done with warp shuffles
//     (3 barriers). Block 0 also zeroes g_diag/out and writes g_inv*.
// ---------------------------------------------------------------------------
__global__ __launch_bounds__(256)
void k_seg(const float* __restrict__ im, const float* __restrict__ s,
           const int* __restrict__ ncl, const int* __restrict__ nca,
           float* __restrict__ out) {
    int b = blockIdx.x;
    bool isB = (b >= NCH_A);
    int cb = isB ? b - NCH_A : b;
    int Rtot = isB ? ROWS_B : ROWS_A;
    int r0 = cb * CHUNK;
    int t = threadIdx.x;
    int lane = t & 31, wid = t >> 5;

    int nrows = Rtot - r0; if (nrows > CHUNK) nrows = CHUNK;

    // ---- batch 1: rows 0..7, front-batched (independent of the scan) ----
    const float4* src = (const float4*)(isB ? s : im) + (size_t)r0 * D4 + t;
    float4 v[8];
#pragma unroll
    for (int u = 0; u < 8; u++)
        v[u] = (u < nrows) ? src[(size_t)u * D4]
                           : make_float4(0.f, 0.f, 0.f, 0.f);

    // ---- warp-shuffle prefix scan of this side's counts (3 barriers) ----
    __shared__ int wsum[8];
    __shared__ int soff[N_G + 1];
    const int* cnts = isB ? nca : ncl;
    int x = cnts[t];
    if (b == 0) {
        g_diag[t] = 0.f;
        g_invA[t] = 1.f / (float)ncl[t];
        g_invB[t] = 1.f / (float)nca[t];
        if (t == 0) out[0] = 0.f;
    }
#pragma unroll
    for (int d = 1; d < 32; d <<= 1) {
        int n = __shfl_up_sync(0xFFFFFFFF, x, d);
        if (lane >= d) x += n;
    }
    if (lane == 31) wsum[wid] = x;
    __syncthreads();
    if (wid == 0) {
        int w = (lane < 8) ? wsum[lane] : 0;
#pragma unroll
        for (int d = 1; d < 8; d <<= 1) {
            int n = __shfl_up_sync(0xFFFFFFFF, w, d);
            if (lane >= d) w += n;
        }
        if (lane < 8) wsum[lane] = w;
    }
    __syncthreads();
    int basew = (wid > 0) ? wsum[wid - 1] : 0;
    soff[t + 1] = basew + x;
    if (t == 0) soff[0] = 0;
    __syncthreads();

    // ---- find group of r0 (uniform across CTA) ----
    int lo = 0, hi = N_G - 1;
    while (lo < hi) {
        int mid = (lo + hi + 1) >> 1;
        if (soff[mid] <= r0) lo = mid; else hi = mid - 1;
    }
    int gidx = lo;
    int gend = soff[gidx + 1];
    float* gs = isB ? g_Bsum : g_Asum;

    float4 acc = make_float4(0.f, 0.f, 0.f, 0.f);
    // ---- walk batch 1 ----
#pragma unroll
    for (int u = 0; u < 8; u++) {
        if (u < nrows && r0 + u == gend) {
            float* p = gs + (size_t)gidx * D + t * 4;
            atomicAdd(p + 0, acc.x); atomicAdd(p + 1, acc.y);
            atomicAdd(p + 2, acc.z); atomicAdd(p + 3, acc.w);
            acc = make_float4(0.f, 0.f, 0.f, 0.f);
            gidx++; gend = soff[gidx + 1];
        }
        acc.x += v[u].x; acc.y += v[u].y; acc.z += v[u].z; acc.w += v[u].w;
    }
    // ---- batch 2: rows 8..15, front-batched ----
#pragma unroll
    for (int u = 0; u < 8; u++)
        v[u] = (8 + u < nrows) ? src[(size_t)(8 + u) * D4]
                               : make_float4(0.f, 0.f, 0.f, 0.f);
#pragma unroll
    for (int u = 8; u < CHUNK; u++) {
        if (u < nrows && r0 + u == gend) {
            float* p = gs + (size_t)gidx * D + t * 4;
            atomicAdd(p + 0, acc.x); atomicAdd(p + 1, acc.y);
            atomicAdd(p + 2, acc.z); atomicAdd(p + 3, acc.w);
            acc = make_float4(0.f, 0.f, 0.f, 0.f);
            gidx++; gend = soff[gidx + 1];
        }
        acc.x += v[u - 8].x; acc.y += v[u - 8].y;
        acc.z += v[u - 8].z; acc.w += v[u - 8].w;
    }
    float* p = gs + (size_t)gidx * D + t * 4;
    atomicAdd(p + 0, acc.x); atomicAdd(p + 1, acc.y);
    atomicAdd(p + 2, acc.z); atomicAdd(p + 3, acc.w);
}

// ---------------------------------------------------------------------------
// K2: split-K GEMM with packed fp32x2 FFMA.
//     grid (4,4,16), 256 threads, 64x64 tile, 4x4 micro per thread held as
//     2 row-pairs x 4 cols of f32x2 accumulators.
// ---------------------------------------------------------------------------
__global__ __launch_bounds__(256)
void k_gemm() {
    __shared__ float As[BK][BM];
    __shared__ float Bs[BK][BN];

    int ib = blockIdx.x, jb = blockIdx.y, kz = blockIdx.z;
    int tid = threadIdx.x;
    int tx = tid & 15;
    int ty = tid >> 4;
    int lm = tid & 63;
    int lk = (tid >> 6) << 2;

    const float4* Ag = (const float4*)g_Asum;
    const float4* Bg = (const float4*)g_Bsum;

    unsigned long long accp[2][4];
#pragma unroll
    for (int rp = 0; rp < 2; rp++)
#pragma unroll
        for (int cc = 0; cc < 4; cc++) accp[rp][cc] = pack2(0.f, 0.f);

    int k0base = kz * KSLICE;
    for (int kc = 0; kc < KSLICE; kc += BK) {
        int kq = (k0base + kc + lk) >> 2;
        float4 av = Ag[(ib * BM + lm) * D4 + kq];
        float4 bv = Bg[(jb * BN + lm) * D4 + kq];
        __syncthreads();
        As[lk + 0][lm] = av.x; As[lk + 1][lm] = av.y;
        As[lk + 2][lm] = av.z; As[lk + 3][lm] = av.w;
        Bs[lk + 0][lm] = bv.x; Bs[lk + 1][lm] = bv.y;
        Bs[lk + 2][lm] = bv.z; Bs[lk + 3][lm] = bv.w;
        __syncthreads();

#pragma unroll
        for (int kk = 0; kk < BK; kk++) {
            float4 a4 = *(const float4*)&As[kk][ty << 2];
            float4 b4 = *(const float4*)&Bs[kk][tx << 2];
            unsigned long long a01 = pack2(a4.x, a4.y);
            unsigned long long a23 = pack2(a4.z, a4.w);
            unsigned long long bb0 = pack2(b4.x, b4.x);
            unsigned long long bb1 = pack2(b4.y, b4.y);
            unsigned long long bb2 = pack2(b4.z, b4.z);
            unsigned long long bb3 = pack2(b4.w, b4.w);
            accp[0][0] = ffma2(a01, bb0, accp[0][0]);
            accp[0][1] = ffma2(a01, bb1, accp[0][1]);
            accp[0][2] = ffma2(a01, bb2, accp[0][2]);
            accp[0][3] = ffma2(a01, bb3, accp[0][3]);
            accp[1][0] = ffma2(a23, bb0, accp[1][0]);
            accp[1][1] = ffma2(a23, bb1, accp[1][1]);
            accp[1][2] = ffma2(a23, bb2, accp[1][2]);
            accp[1][3] = ffma2(a23, bb3, accp[1][3]);
        }
    }

    float o[4][4];
#pragma unroll
    for (int rp = 0; rp < 2; rp++)
#pragma unroll
        for (int cc = 0; cc < 4; cc++)
            unpack2(o[2 * rp][cc], o[2 * rp + 1][cc], accp[rp][cc]);

    float* Sp = g_Sp[kz];
#pragma unroll
    for (int r = 0; r < 4; r++) {
        int i = ib * BM + (ty << 2) + r;
        float4 vv = make_float4(o[r][0], o[r][1], o[r][2], o[r][3]);
        *(float4*)&Sp[i * N_G + jb * BN + (tx << 2)] = vv;
    }

    if (ib == jb && tx == ty) {
#pragma unroll
        for (int r = 0; r < 4; r++)
            atomicAdd(&g_diag[ib * BM + (ty << 2) + r], o[r][r]);
    }
}

// ---------------------------------------------------------------------------
// K3: loss (count-scaling folded in) + FULL re-zero of g_Asum/g_Bsum.
//     grid 64 x 256; each thread = one (i, j-quad), 16 independent LDG.128.
//     Each thread zeroes 4 float4s per buffer (16384 x 4 = 65536 quads
//     = N_G*D floats -> complete coverage).
// ---------------------------------------------------------------------------
__global__ __launch_bounds__(256)
void k_loss(float* __restrict__ out) {
    int qid = blockIdx.x * 256 + threadIdx.x;   // [0, 16384)
    int i  = qid >> 6;                          // row
    int j0 = (qid & 63) << 2;                   // first col of the quad

    float4 sv = make_float4(0.f, 0.f, 0.f, 0.f);
#pragma unroll
    for (int z = 0; z < KSPLIT; z++) {
        float4 pv = *(const float4*)&g_Sp[z][i * N_G + j0];
        sv.x += pv.x; sv.y += pv.y; sv.z += pv.z; sv.w += pv.w;
    }

    float ai = g_invA[i];
    float bi = g_invB[i];
    float di = g_diag[i] * ai * bi;

    float4 dj4 = *(const float4*)&g_diag[j0];
    float4 aj4 = *(const float4*)&g_invA[j0];
    float4 bj4 = *(const float4*)&g_invB[j0];

    float sum = 0.f;
    {
        float S, dj;
        S = sv.x * ai * bj4.x; dj = dj4.x * aj4.x * bj4.x;
        if (i != j0 + 0) sum += fmaxf(S - di, 0.f) + fmaxf(S - dj, 0.f);
        S = sv.y * ai * bj4.y; dj = dj4.y * aj4.y * bj4.y;
        if (i != j0 + 1) sum += fmaxf(S - di, 0.f) + fmaxf(S - dj, 0.f);
        S = sv.z * ai * bj4.z; dj = dj4.z * aj4.z * bj4.z;
        if (i != j0 + 2) sum += fmaxf(S - di, 0.f) + fmaxf(S - dj, 0.f);
        S = sv.w * ai * bj4.w; dj = dj4.w * aj4.w * bj4.w;
        if (i != j0 + 3) sum += fmaxf(S - di, 0.f) + fmaxf(S - dj, 0.f);
    }

    // FULL re-zero of accumulators for the next graph replay.
    float4 z4 = make_float4(0.f, 0.f, 0.f, 0.f);
#pragma unroll
    for (int u = 0; u < 4; u++) {
        ((float4*)g_Asum)[qid + u * 16384] = z4;
        ((float4*)g_Bsum)[qid + u * 16384] = z4;
    }

#pragma unroll
    for (int st = 16; st > 0; st >>= 1)
        sum += __shfl_xor_sync(0xFFFFFFFF, sum, st);

    __shared__ float red[8];
    int t = threadIdx.x;
    if ((t & 31) == 0) red[t >> 5] = sum;
    __syncthreads();
    if (t < 8) {
        float v = red[t];
#pragma unroll
        for (int st = 4; st > 0; st >>= 1)
            v += __shfl_xor_sync(0xFF, v, st);
        if (t == 0) atomicAdd(out, v);
    }
}

// ---------------------------------------------------------------------------
extern "C" void kernel_launch(void* const* d_in, const int* in_sizes, int n_in,
                              void* d_out, int out_size) {
    const float* im  = (const float*)d_in[0];
    const float* s   = (const float*)d_in[1];
    const int*   ncl = (const int*)d_in[2];
    const int*   nca = (const int*)d_in[3];
    float* out = (float*)d_out;

    k_seg<<<NCH_A + NCH_B, 256>>>(im, s, ncl, nca, out);
    dim3 g2(N_G / BM, N_G / BN, KSPLIT);
    k_gemm<<<g2, 256>>>();
    k_loss<<<64, 256>>>(out);
}